// round 14
// baseline (speedup 1.0000x reference)
#include <cuda_runtime.h>
#include <cuda_fp16.h>
#include <cstdint>
#include <math.h>

#define Bsz 2
#define Tseq 4096
#define Cdim 768
#define Hn 12
#define HD 64
#define C3 (3*Cdim)
#define Mrows (Bsz*Tseq)   // 8192

// ---------------- scratch (no allocs allowed) ----------------
__device__ __align__(16) __half g_xf  [(size_t)Mrows * Cdim];
__device__ __align__(16) __half g_qkvf[(size_t)Mrows * C3];
__device__ __align__(16) __half g_yf  [(size_t)Mrows * Cdim];
__device__ __align__(16) __half g_wqf [(size_t)C3 * Cdim];   // qkv_w^T  [N,K] fp16
__device__ __align__(16) __half g_wof [(size_t)Cdim * Cdim]; // out_w^T  [N,K] fp16

// ================= portable PTX helpers =================
__device__ __forceinline__ uint32_t smem_u32(const void* p) {
    uint32_t a;
    asm("{ .reg .u64 t; cvta.to.shared.u64 t, %1; cvt.u32.u64 %0, t; }" : "=r"(a) : "l"(p));
    return a;
}
#define CP_ASYNC16(dst, src) \
    asm volatile("cp.async.cg.shared.global [%0], [%1], 16;" :: "r"(dst), "l"(src) : "memory")
#define CP_COMMIT() asm volatile("cp.async.commit_group;" ::: "memory")
#define CP_WAIT(n)  asm volatile("cp.async.wait_group %0;" :: "n"(n) : "memory")

__device__ __forceinline__ void ldsm_x4(uint32_t& r0, uint32_t& r1, uint32_t& r2, uint32_t& r3,
                                        uint32_t addr) {
    asm volatile("ldmatrix.sync.aligned.m8n8.x4.shared.b16 {%0,%1,%2,%3}, [%4];"
                 : "=r"(r0), "=r"(r1), "=r"(r2), "=r"(r3) : "r"(addr));
}
__device__ __forceinline__ void ldsm_x4_t(uint32_t& r0, uint32_t& r1, uint32_t& r2, uint32_t& r3,
                                          uint32_t addr) {
    asm volatile("ldmatrix.sync.aligned.m8n8.x4.trans.shared.b16 {%0,%1,%2,%3}, [%4];"
                 : "=r"(r0), "=r"(r1), "=r"(r2), "=r"(r3) : "r"(addr));
}
__device__ __forceinline__ void mma16816(float* d, const uint32_t* a, const uint32_t* b) {
    asm volatile(
        "mma.sync.aligned.m16n8k16.row.col.f32.f16.f16.f32 "
        "{%0,%1,%2,%3}, {%4,%5,%6,%7}, {%8,%9}, {%0,%1,%2,%3};"
        : "+f"(d[0]), "+f"(d[1]), "+f"(d[2]), "+f"(d[3])
        : "r"(a[0]), "r"(a[1]), "r"(a[2]), "r"(a[3]), "r"(b[0]), "r"(b[1]));
}
__device__ __forceinline__ uint32_t packhf(float lo, float hi) {
    uint32_t d;
    asm("cvt.rn.f16x2.f32 %0, %1, %2;" : "=r"(d) : "f"(hi), "f"(lo));
    return d;
}
__device__ __forceinline__ uint32_t ex2_f16x2(uint32_t a) {
    uint32_t d;
    asm("ex2.approx.f16x2 %0, %1;" : "=r"(d) : "r"(a));
    return d;
}

// ================= fused prep: round x + round-transpose both weights =================
#define XB  ((Mrows*Cdim/4 + 255)/256)   // 6144
#define WQB ((C3/32)*(Cdim/32))          // 1728
#define WOB ((Cdim/32)*(Cdim/32))        // 576

__global__ __launch_bounds__(256)
void prep_kernel(const float* __restrict__ x, __half* __restrict__ xf,
                 const float* __restrict__ wq, __half* __restrict__ wqf,
                 const float* __restrict__ wo, __half* __restrict__ wof)
{
    const int bid = blockIdx.x;
    if (bid < XB) {
        int i4 = bid * 256 + threadIdx.x;
        if (i4 >= Mrows * Cdim / 4) return;
        float4 v = ((const float4*)x)[i4];
        uint2 o;
        o.x = packhf(v.x, v.y);
        o.y = packhf(v.z, v.w);
        ((uint2*)xf)[i4] = o;
        return;
    }
    const float* W; __half* Tf; int K, N, bx, by;
    if (bid < XB + WQB) {
        int j = bid - XB;
        W = wq; Tf = wqf; K = Cdim; N = C3;
        bx = j % (C3/32); by = j / (C3/32);
    } else {
        int j = bid - XB - WQB;
        W = wo; Tf = wof; K = Cdim; N = Cdim;
        bx = j % (Cdim/32); by = j / (Cdim/32);
    }
    __shared__ float t[32][33];
    const int n0 = bx * 32, k0 = by * 32;
    const int tx = threadIdx.x & 31, ty = (threadIdx.x >> 5);
    #pragma unroll
    for (int j = 0; j < 4; j++)
        t[ty + j*8][tx] = W[(size_t)(k0 + ty + j*8) * N + n0 + tx];
    __syncthreads();
    #pragma unroll
    for (int j = 0; j < 4; j++)
        Tf[(size_t)(n0 + ty + j*8) * K + k0 + tx] = __float2half_rn(t[tx][ty + j*8]);
}

// ================= warp-MMA fp16 GEMM (swizzled, K-step 64, 3-stage ring) =================
// 128x128 block tile, 4 warps (2m x 2n), warp tile 64x64.
#define GBM 128
#define GBN 128
#define GBK 64
#define GTILE 16384              // 128 rows x 128B (SW128)
#define GSTAGE (2*GTILE)         // Af | Bf = 32768 B
#define GEMM_SMEM (3*GSTAGE)     // 98304 B

template<bool F16OUT>
__global__ __launch_bounds__(128, 2)
void gemm_mma(const __half* __restrict__ Af, const __half* __restrict__ Bf,
              const float* __restrict__ bias, float* __restrict__ C,
              __half* __restrict__ Cf,
              int M, int N, int K)
{
    extern __shared__ __align__(16) char gsm[];
    const uint32_t smBase = smem_u32(gsm);

    const int tid  = threadIdx.x;
    const int lane = tid & 31;
    const int wid  = tid >> 5;        // 0..3
    const int wm   = wid & 1;
    const int wn   = wid >> 1;
    const int rowBase = blockIdx.y * GBM;
    const int colBase = blockIdx.x * GBN;

    const int mat = lane >> 3, r8 = lane & 7;
    const uint32_t pat = (uint32_t)r8 << 4;

    uint32_t aRow[4], bRow[4], acol[4], bcol[4];
    #pragma unroll
    for (int mt = 0; mt < 4; mt++)
        aRow[mt] = (uint32_t)(wm * 64 + mt * 16 + (mat & 1) * 8 + r8) * 128;
    #pragma unroll
    for (int nt2 = 0; nt2 < 4; nt2++)
        bRow[nt2] = (uint32_t)(wn * 64 + nt2 * 16 + (mat >> 1) * 8 + r8) * 128;
    #pragma unroll
    for (int kk = 0; kk < 4; kk++) {
        acol[kk] = (uint32_t)(kk * 32 + (mat >> 1) * 16) ^ pat;
        bcol[kk] = (uint32_t)(kk * 32 + (mat & 1) * 16) ^ pat;
    }

    float acc[4][8][4];
    #pragma unroll
    for (int i = 0; i < 4; i++)
        #pragma unroll
        for (int j = 0; j < 8; j++)
            #pragma unroll
            for (int q = 0; q < 4; q++) acc[i][j][q] = 0.f;

    const int KC = K / GBK;   // 12

    auto issue_tile = [&](int it) {
        const uint32_t stOff = (uint32_t)(it % 3) * GSTAGE;
        const int kc = it;
        #pragma unroll
        for (int i = 0; i < 16; i++) {
            const int idx  = tid + i * 128;
            const int tile = idx >> 10;
            const int rem  = idx & 1023;
            const int r    = rem >> 3;
            const int c8   = rem & 7;
            const uint32_t dst = smBase + stOff + (uint32_t)tile * GTILE
                               + (uint32_t)(r * 128 + ((c8 * 16) ^ ((r & 7) << 4)));
            const __half* src = tile ? (Bf + (size_t)(colBase + r) * K + kc * GBK + c8 * 8)
                                     : (Af + (size_t)(rowBase + r) * K + kc * GBK + c8 * 8);
            CP_ASYNC16(dst, src);
        }
        CP_COMMIT();
    };

    issue_tile(0);
    issue_tile(1);

    for (int it = 0; it < KC; ++it) {
        if (it + 1 < KC) { CP_WAIT(1); } else { CP_WAIT(0); }
        __syncthreads();
        if (it + 2 < KC) issue_tile(it + 2);

        const uint32_t stOff = smBase + (uint32_t)(it % 3) * GSTAGE;
        #pragma unroll
        for (int kk = 0; kk < 4; kk++) {
            uint32_t af[4][4], bf[8][2];
            #pragma unroll
            for (int mt = 0; mt < 4; mt++)
                ldsm_x4(af[mt][0], af[mt][1], af[mt][2], af[mt][3],
                        stOff + aRow[mt] + acol[kk]);
            #pragma unroll
            for (int nt2 = 0; nt2 < 4; nt2++) {
                uint32_t r0, r1, r2, r3;
                ldsm_x4(r0, r1, r2, r3, stOff + GTILE + bRow[nt2] + bcol[kk]);
                bf[nt2*2][0] = r0; bf[nt2*2][1] = r1;
                bf[nt2*2+1][0] = r2; bf[nt2*2+1][1] = r3;
            }
            #pragma unroll
            for (int mt = 0; mt < 4; mt++)
                #pragma unroll
                for (int nt = 0; nt < 8; nt++)
                    mma16816(acc[mt][nt], af[mt], bf[nt]);
        }
    }

    const int g = lane >> 2, t = lane & 3;
    #pragma unroll
    for (int mt = 0; mt < 4; mt++) {
        #pragma unroll
        for (int nt = 0; nt < 8; nt++) {
            const int col = colBase + wn * 64 + nt * 8 + t * 2;
            const float b0 = bias[col], b1 = bias[col + 1];
            const int row0 = rowBase + wm * 64 + mt * 16 + g;
            float v0 = acc[mt][nt][0] + b0, v1 = acc[mt][nt][1] + b1;
            float v2 = acc[mt][nt][2] + b0, v3 = acc[mt][nt][3] + b1;
            if (F16OUT) {
                *(uint32_t*)(Cf + (size_t)row0 * N + col)       = packhf(v0, v1);
                *(uint32_t*)(Cf + (size_t)(row0 + 8) * N + col) = packhf(v2, v3);
            } else {
                *(float2*)&C[(size_t)row0 * N + col]       = make_float2(v0, v1);
                *(float2*)&C[(size_t)(row0 + 8) * N + col] = make_float2(v2, v3);
            }
        }
    }
}

// ================= tensor-core causal flash attention (fp16, swizzled) =================
// CTA: 256 queries, 8 warps x 32 rows (2 m-frags/warp). K-tiles of 64, 3-stage ring.
// Halved K/V-tile visits per unit work vs BM=128 -> ~17% less crossbar traffic.
#define TILEB 8192                    // 64 rows x 128B (SW128)
#define BUFB  (2*TILEB)               // K, V = 16384 B
#define QOFF  (3u*BUFB)               // Q region after ring: 256 rows x 128B = 32 KB
#define ATT_SMEM (3*BUFB + 32768)     // 81920 B
#define ESC 0.18033688f               // 0.125 * log2(e)

__global__ __launch_bounds__(256, 1)
void attn_mma(const __half* __restrict__ qkv, __half* __restrict__ yf)
{
    extern __shared__ __align__(16) char sm[];
    const uint32_t smBase = smem_u32(sm);

    const int tid  = threadIdx.x;
    const int lane = tid & 31;
    const int wm   = tid >> 5;          // 0..7, rows wm*32..wm*32+31
    const int bh = blockIdx.y;
    const int b  = bh / Hn;
    const int h  = bh % Hn;
    const int q0 = (gridDim.x - 1 - blockIdx.x) * 256;   // big tiles first

    const int mat = lane >> 3, r8 = lane & 7;
    const int g = lane >> 2, t = lane & 3;
    const uint32_t pat = (uint32_t)r8 << 4;

    const int nk = q0 / 64 + 4;

    // ---- stage Q (256 rows) into Q region: 2048 chunks / 256 threads ----
    #pragma unroll
    for (int i = 0; i < 8; i++) {
        const int idx = tid + i * 256;
        const int r   = idx >> 3;
        const int c8  = idx & 7;
        const uint32_t dst = smBase + QOFF
                           + (uint32_t)(r * 128 + ((c8 * 16) ^ ((r & 7) << 4)));
        const __half* src = qkv + (size_t)(b * Tseq + q0 + r) * C3 + h * HD + c8 * 8;
        CP_ASYNC16(dst, src);
    }
    CP_COMMIT();

    uint32_t kRow[4], kcol[4], qcol[4], vcol[4];
    #pragma unroll
    for (int nt2 = 0; nt2 < 4; nt2++) {
        kRow[nt2] = (uint32_t)(nt2 * 16 + (mat >> 1) * 8 + r8) * 128;
        vcol[nt2] = (uint32_t)(nt2 * 32 + (mat >> 1) * 16) ^ pat;
    }
    #pragma unroll
    for (int ks = 0; ks < 4; ks++) {
        kcol[ks] = (uint32_t)(ks * 32 + (mat & 1) * 16) ^ pat;
        qcol[ks] = (uint32_t)(ks * 32 + (mat >> 1) * 16) ^ pat;
    }
    const uint32_t vRow = (uint32_t)((mat & 1) * 8 + r8) * 128;

    auto fill = [&](int it) {
        const int k0 = it * 64;
        const uint32_t bufOff = (uint32_t)(it % 3) * BUFB;
        #pragma unroll
        for (int i = 0; i < 4; i++) {
            const int idx = tid + i * 256;       // 1024 chunks
            const int tile = idx >> 9;           // 0 K, 1 V
            const int r    = (idx >> 3) & 63;
            const int c8   = idx & 7;
            const uint32_t dst = smBase + bufOff + (uint32_t)tile * TILEB
                               + (uint32_t)(r * 128 + ((c8 * 16) ^ ((r & 7) << 4)));
            const __half* src = qkv + (size_t)(b * Tseq + k0 + r) * C3 + h * HD + c8 * 8
                              + (tile ? 2 * Cdim : Cdim);
            CP_ASYNC16(dst, src);
        }
        CP_COMMIT();
    };

    fill(0);
    fill(1);

    CP_WAIT(2);          // Q group complete
    __syncthreads();

    uint32_t qf[2][4][4];
    #pragma unroll
    for (int mt = 0; mt < 2; mt++) {
        const uint32_t qRow = (uint32_t)(wm * 32 + mt * 16 + (mat & 1) * 8 + r8) * 128;
        #pragma unroll
        for (int ks = 0; ks < 4; ks++)
            ldsm_x4(qf[mt][ks][0], qf[mt][ks][1], qf[mt][ks][2], qf[mt][ks][3],
                    smBase + QOFF + qRow + qcol[ks]);
    }

    float O[2][8][4];
    #pragma unroll
    for (int mt = 0; mt < 2; mt++)
        #pragma unroll
        for (int nt = 0; nt < 8; nt++)
            #pragma unroll
            for (int q = 0; q < 4; q++) O[mt][nt][q] = 0.f;
    float mm[2][2], ll[2][2];
    #pragma unroll
    for (int mt = 0; mt < 2; mt++) { mm[mt][0] = mm[mt][1] = -1e30f; ll[mt][0] = ll[mt][1] = 0.f; }

    const uint32_t onesb[2] = {0x3C003C00u, 0x3C003C00u};   // fp16 1.0 x4

    for (int it = 0; it < nk; ++it) {
        if (it < nk - 1) { CP_WAIT(1); } else { CP_WAIT(0); }
        __syncthreads();
        if (it + 2 < nk) fill(it + 2);

        const int k0 = it * 64;
        const uint32_t bufO = smBase + (uint32_t)(it % 3) * BUFB;

        // ---- S = Qf·Kf^T (both m-frags share each K fragment) ----
        float S[2][8][4];
        #pragma unroll
        for (int mt = 0; mt < 2; mt++)
            #pragma unroll
            for (int nt = 0; nt < 8; nt++)
                #pragma unroll
                for (int q = 0; q < 4; q++) S[mt][nt][q] = 0.f;

        #pragma unroll
        for (int ks = 0; ks < 4; ks++) {
            uint32_t kf[8][2];
            #pragma unroll
            for (int nt2 = 0; nt2 < 4; nt2++) {
                uint32_t r0, r1, r2, r3;
                ldsm_x4(r0, r1, r2, r3, bufO + kRow[nt2] + kcol[ks]);
                kf[nt2*2][0] = r0; kf[nt2*2][1] = r1;
                kf[nt2*2+1][0] = r2; kf[nt2*2+1][1] = r3;
            }
            #pragma unroll
            for (int mt = 0; mt < 2; mt++)
                #pragma unroll
                for (int nt = 0; nt < 8; nt++)
                    mma16816(S[mt][nt], qf[mt][ks], kf[nt]);
        }

        // ---- causal mask (diagonal tiles only) ----
        if (k0 + 63 > q0 + wm * 32) {
            #pragma unroll
            for (int mt = 0; mt < 2; mt++) {
                const int rg0 = q0 + wm * 32 + mt * 16 + g;
                const int rg1 = rg0 + 8;
                #pragma unroll
                for (int nt = 0; nt < 8; nt++) {
                    const int c = k0 + nt * 8 + t * 2;
                    if (c     > rg0) S[mt][nt][0] = -1e30f;
                    if (c + 1 > rg0) S[mt][nt][1] = -1e30f;
                    if (c     > rg1) S[mt][nt][2] = -1e30f;
                    if (c + 1 > rg1) S[mt][nt][3] = -1e30f;
                }
            }
        }

        // ---- online softmax + P fragments (per m-frag) ----
        uint32_t pf[2][4][4];
        #pragma unroll
        for (int mt = 0; mt < 2; mt++) {
            float mx0 = -1e30f, mx1 = -1e30f;
            #pragma unroll
            for (int nt = 0; nt < 8; nt++) {
                mx0 = fmaxf(mx0, fmaxf(S[mt][nt][0], S[mt][nt][1]));
                mx1 = fmaxf(mx1, fmaxf(S[mt][nt][2], S[mt][nt][3]));
            }
            mx0 = fmaxf(mx0, __shfl_xor_sync(0xffffffffu, mx0, 1));
            mx0 = fmaxf(mx0, __shfl_xor_sync(0xffffffffu, mx0, 2));
            mx1 = fmaxf(mx1, __shfl_xor_sync(0xffffffffu, mx1, 1));
            mx1 = fmaxf(mx1, __shfl_xor_sync(0xffffffffu, mx1, 2));

            const float mn0 = fmaxf(mm[mt][0], mx0);
            const float mn1 = fmaxf(mm[mt][1], mx1);
            const float cr0 = exp2f((mm[mt][0] - mn0) * ESC);
            const float cr1 = exp2f((mm[mt][1] - mn1) * ESC);
            mm[mt][0] = mn0; mm[mt][1] = mn1;
            #pragma unroll
            for (int nt = 0; nt < 8; nt++) {
                O[mt][nt][0] *= cr0; O[mt][nt][1] *= cr0;
                O[mt][nt][2] *= cr1; O[mt][nt][3] *= cr1;
            }

            const float nE0 = mn0 * ESC, nE1 = mn1 * ESC;
            #pragma unroll
            for (int kk = 0; kk < 4; kk++) {
                pf[mt][kk][0] = ex2_f16x2(packhf(fmaf(S[mt][2*kk][0],   ESC, -nE0), fmaf(S[mt][2*kk][1],   ESC, -nE0)));
                pf[mt][kk][1] = ex2_f16x2(packhf(fmaf(S[mt][2*kk][2],   ESC, -nE1), fmaf(S[mt][2*kk][3],   ESC, -nE1)));
                pf[mt][kk][2] = ex2_f16x2(packhf(fmaf(S[mt][2*kk+1][0], ESC, -nE0), fmaf(S[mt][2*kk+1][1], ESC, -nE0)));
                pf[mt][kk][3] = ex2_f16x2(packhf(fmaf(S[mt][2*kk+1][2], ESC, -nE1), fmaf(S[mt][2*kk+1][3], ESC, -nE1)));
            }

            float lac[4] = {0.f, 0.f, 0.f, 0.f};
            #pragma unroll
            for (int kk = 0; kk < 4; kk++) mma16816(lac, pf[mt][kk], onesb);
            ll[mt][0] = ll[mt][0] * cr0 + lac[0];
            ll[mt][1] = ll[mt][1] * cr1 + lac[2];
        }

        // ---- O += Pf·Vf (both m-frags share each V fragment) ----
        #pragma unroll
        for (int kk = 0; kk < 4; kk++) {
            uint32_t vf[8][2];
            #pragma unroll
            for (int nd2 = 0; nd2 < 4; nd2++) {
                uint32_t r0, r1, r2, r3;
                ldsm_x4_t(r0, r1, r2, r3, bufO + TILEB + vRow + kk * 2048 + vcol[nd2]);
                vf[nd2*2][0] = r0; vf[nd2*2][1] = r1;
                vf[nd2*2+1][0] = r2; vf[nd2*2+1][1] = r3;
            }
            #pragma unroll
            for (int mt = 0; mt < 2; mt++)
                #pragma unroll
                for (int nd = 0; nd < 8; nd++)
                    mma16816(O[mt][nd], pf[mt][kk], vf[nd]);
        }
    }

    // ---- epilogue: normalize, round to fp16, store ----
    #pragma unroll
    for (int mt = 0; mt < 2; mt++) {
        const float i0 = 1.f / ll[mt][0], i1 = 1.f / ll[mt][1];
        const int rg0 = q0 + wm * 32 + mt * 16 + g;
        const size_t base0 = (size_t)(b * Tseq + rg0) * Cdim + h * HD;
        const size_t base1 = (size_t)(b * Tseq + rg0 + 8) * Cdim + h * HD;
        #pragma unroll
        for (int nt = 0; nt < 8; nt++) {
            const int col = nt * 8 + t * 2;
            *(uint32_t*)(yf + base0 + col) = packhf(O[mt][nt][0] * i0, O[mt][nt][1] * i0);
            *(uint32_t*)(yf + base1 + col) = packhf(O[mt][nt][2] * i1, O[mt][nt][3] * i1);
        }
    }
}

// ---------------- launch ----------------
extern "C" void kernel_launch(void* const* d_in, const int* in_sizes, int n_in,
                              void* d_out, int out_size)
{
    const float* x     = (const float*)d_in[0];
    const float* qkv_w = (const float*)d_in[1];
    const float* qkv_b = (const float*)d_in[2];
    const float* out_w = (const float*)d_in[3];
    const float* out_b = (const float*)d_in[4];
    float* out = (float*)d_out;

    __half *xf, *qkvf, *yf, *wqf, *wof;
    cudaGetSymbolAddress((void**)&xf,   g_xf);
    cudaGetSymbolAddress((void**)&qkvf, g_qkvf);
    cudaGetSymbolAddress((void**)&yf,   g_yf);
    cudaGetSymbolAddress((void**)&wqf,  g_wqf);
    cudaGetSymbolAddress((void**)&wof,  g_wof);

    cudaFuncSetAttribute(gemm_mma<true>,  cudaFuncAttributeMaxDynamicSharedMemorySize, GEMM_SMEM);
    cudaFuncSetAttribute(gemm_mma<false>, cudaFuncAttributeMaxDynamicSharedMemorySize, GEMM_SMEM);
    cudaFuncSetAttribute(attn_mma, cudaFuncAttributeMaxDynamicSharedMemorySize, ATT_SMEM);

    const int M = Mrows;   // 8192

    // 0) fused prep
    prep_kernel<<<XB + WQB + WOB, 256>>>(x, xf, qkv_w, wqf, out_w, wof);

    // 1) QKV projection -> fp16 qkv
    gemm_mma<true><<<dim3(C3 / GBN, M / GBM), 128, GEMM_SMEM>>>(
        xf, wqf, qkv_b, nullptr, qkvf, M, C3, Cdim);

    // 2) causal attention -> fp16 y
    attn_mma<<<dim3(Tseq / 256, Bsz * Hn), 256, ATT_SMEM>>>(qkvf, yf);

    // 3) output projection -> fp32 out
    gemm_mma<false><<<dim3(Cdim / GBN, M / GBM), 128, GEMM_SMEM>>>(
        yf, wof, out_b, out, nullptr, M, Cdim, Cdim);
}

// round 15
// speedup vs baseline: 1.0184x; 1.0184x over previous
#include <cuda_runtime.h>
#include <cuda_fp16.h>
#include <cstdint>
#include <math.h>

#define Bsz 2
#define Tseq 4096
#define Cdim 768
#define Hn 12
#define HD 64
#define C3 (3*Cdim)
#define Mrows (Bsz*Tseq)   // 8192

// ---------------- scratch (no allocs allowed) ----------------
__device__ __align__(16) __half g_xf  [(size_t)Mrows * Cdim];
__device__ __align__(16) __half g_qkvf[(size_t)Mrows * C3];
__device__ __align__(16) __half g_yf  [(size_t)Mrows * Cdim];
__device__ __align__(16) __half g_wqf [(size_t)C3 * Cdim];   // qkv_w^T  [N,K] fp16
__device__ __align__(16) __half g_wof [(size_t)Cdim * Cdim]; // out_w^T  [N,K] fp16

// ================= portable PTX helpers =================
__device__ __forceinline__ uint32_t smem_u32(const void* p) {
    uint32_t a;
    asm("{ .reg .u64 t; cvta.to.shared.u64 t, %1; cvt.u32.u64 %0, t; }" : "=r"(a) : "l"(p));
    return a;
}
#define CP_ASYNC16(dst, src) \
    asm volatile("cp.async.cg.shared.global [%0], [%1], 16;" :: "r"(dst), "l"(src) : "memory")
#define CP_COMMIT() asm volatile("cp.async.commit_group;" ::: "memory")
#define CP_WAIT(n)  asm volatile("cp.async.wait_group %0;" :: "n"(n) : "memory")

__device__ __forceinline__ void ldsm_x4(uint32_t& r0, uint32_t& r1, uint32_t& r2, uint32_t& r3,
                                        uint32_t addr) {
    asm volatile("ldmatrix.sync.aligned.m8n8.x4.shared.b16 {%0,%1,%2,%3}, [%4];"
                 : "=r"(r0), "=r"(r1), "=r"(r2), "=r"(r3) : "r"(addr));
}
__device__ __forceinline__ void ldsm_x4_t(uint32_t& r0, uint32_t& r1, uint32_t& r2, uint32_t& r3,
                                          uint32_t addr) {
    asm volatile("ldmatrix.sync.aligned.m8n8.x4.trans.shared.b16 {%0,%1,%2,%3}, [%4];"
                 : "=r"(r0), "=r"(r1), "=r"(r2), "=r"(r3) : "r"(addr));
}
__device__ __forceinline__ void mma16816(float* d, const uint32_t* a, const uint32_t* b) {
    asm volatile(
        "mma.sync.aligned.m16n8k16.row.col.f32.f16.f16.f32 "
        "{%0,%1,%2,%3}, {%4,%5,%6,%7}, {%8,%9}, {%0,%1,%2,%3};"
        : "+f"(d[0]), "+f"(d[1]), "+f"(d[2]), "+f"(d[3])
        : "r"(a[0]), "r"(a[1]), "r"(a[2]), "r"(a[3]), "r"(b[0]), "r"(b[1]));
}
__device__ __forceinline__ uint32_t packhf(float lo, float hi) {
    uint32_t d;
    asm("cvt.rn.f16x2.f32 %0, %1, %2;" : "=r"(d) : "f"(hi), "f"(lo));
    return d;
}
__device__ __forceinline__ uint32_t ex2_f16x2(uint32_t a) {
    uint32_t d;
    asm("ex2.approx.f16x2 %0, %1;" : "=r"(d) : "r"(a));
    return d;
}

// ================= fused prep: round x + round-transpose both weights =================
#define XB  ((Mrows*Cdim/4 + 255)/256)   // 6144
#define WQB ((C3/32)*(Cdim/32))          // 1728
#define WOB ((Cdim/32)*(Cdim/32))        // 576

__global__ __launch_bounds__(256)
void prep_kernel(const float* __restrict__ x, __half* __restrict__ xf,
                 const float* __restrict__ wq, __half* __restrict__ wqf,
                 const float* __restrict__ wo, __half* __restrict__ wof)
{
    const int bid = blockIdx.x;
    if (bid < XB) {
        int i4 = bid * 256 + threadIdx.x;
        if (i4 >= Mrows * Cdim / 4) return;
        float4 v = ((const float4*)x)[i4];
        uint2 o;
        o.x = packhf(v.x, v.y);
        o.y = packhf(v.z, v.w);
        ((uint2*)xf)[i4] = o;
        return;
    }
    const float* W; __half* Tf; int K, N, bx, by;
    if (bid < XB + WQB) {
        int j = bid - XB;
        W = wq; Tf = wqf; K = Cdim; N = C3;
        bx = j % (C3/32); by = j / (C3/32);
    } else {
        int j = bid - XB - WQB;
        W = wo; Tf = wof; K = Cdim; N = Cdim;
        bx = j % (Cdim/32); by = j / (Cdim/32);
    }
    __shared__ float t[32][33];
    const int n0 = bx * 32, k0 = by * 32;
    const int tx = threadIdx.x & 31, ty = (threadIdx.x >> 5);
    #pragma unroll
    for (int j = 0; j < 4; j++)
        t[ty + j*8][tx] = W[(size_t)(k0 + ty + j*8) * N + n0 + tx];
    __syncthreads();
    #pragma unroll
    for (int j = 0; j < 4; j++)
        Tf[(size_t)(n0 + ty + j*8) * K + k0 + tx] = __float2half_rn(t[tx][ty + j*8]);
}

// ================= warp-MMA fp16 GEMM (swizzled, K-step 64, 3-stage ring) =================
// 128x128 block tile, 4 warps (2m x 2n), warp tile 64x64.
#define GBM 128
#define GBN 128
#define GBK 64
#define GTILE 16384              // 128 rows x 128B (SW128)
#define GSTAGE (2*GTILE)         // Af | Bf = 32768 B
#define GEMM_SMEM (3*GSTAGE)     // 98304 B

template<bool F16OUT>
__global__ __launch_bounds__(128, 2)
void gemm_mma(const __half* __restrict__ Af, const __half* __restrict__ Bf,
              const float* __restrict__ bias, float* __restrict__ C,
              __half* __restrict__ Cf,
              int M, int N, int K)
{
    extern __shared__ __align__(16) char gsm[];
    const uint32_t smBase = smem_u32(gsm);

    const int tid  = threadIdx.x;
    const int lane = tid & 31;
    const int wid  = tid >> 5;        // 0..3
    const int wm   = wid & 1;
    const int wn   = wid >> 1;
    const int rowBase = blockIdx.y * GBM;
    const int colBase = blockIdx.x * GBN;

    const int mat = lane >> 3, r8 = lane & 7;
    const uint32_t pat = (uint32_t)r8 << 4;

    uint32_t aRow[4], bRow[4], acol[4], bcol[4];
    #pragma unroll
    for (int mt = 0; mt < 4; mt++)
        aRow[mt] = (uint32_t)(wm * 64 + mt * 16 + (mat & 1) * 8 + r8) * 128;
    #pragma unroll
    for (int nt2 = 0; nt2 < 4; nt2++)
        bRow[nt2] = (uint32_t)(wn * 64 + nt2 * 16 + (mat >> 1) * 8 + r8) * 128;
    #pragma unroll
    for (int kk = 0; kk < 4; kk++) {
        acol[kk] = (uint32_t)(kk * 32 + (mat >> 1) * 16) ^ pat;
        bcol[kk] = (uint32_t)(kk * 32 + (mat & 1) * 16) ^ pat;
    }

    float acc[4][8][4];
    #pragma unroll
    for (int i = 0; i < 4; i++)
        #pragma unroll
        for (int j = 0; j < 8; j++)
            #pragma unroll
            for (int q = 0; q < 4; q++) acc[i][j][q] = 0.f;

    const int KC = K / GBK;   // 12

    auto issue_tile = [&](int it) {
        const uint32_t stOff = (uint32_t)(it % 3) * GSTAGE;
        const int kc = it;
        #pragma unroll
        for (int i = 0; i < 16; i++) {
            const int idx  = tid + i * 128;
            const int tile = idx >> 10;
            const int rem  = idx & 1023;
            const int r    = rem >> 3;
            const int c8   = rem & 7;
            const uint32_t dst = smBase + stOff + (uint32_t)tile * GTILE
                               + (uint32_t)(r * 128 + ((c8 * 16) ^ ((r & 7) << 4)));
            const __half* src = tile ? (Bf + (size_t)(colBase + r) * K + kc * GBK + c8 * 8)
                                     : (Af + (size_t)(rowBase + r) * K + kc * GBK + c8 * 8);
            CP_ASYNC16(dst, src);
        }
        CP_COMMIT();
    };

    issue_tile(0);
    issue_tile(1);

    for (int it = 0; it < KC; ++it) {
        if (it + 1 < KC) { CP_WAIT(1); } else { CP_WAIT(0); }
        __syncthreads();
        if (it + 2 < KC) issue_tile(it + 2);

        const uint32_t stOff = smBase + (uint32_t)(it % 3) * GSTAGE;
        #pragma unroll
        for (int kk = 0; kk < 4; kk++) {
            uint32_t af[4][4], bf[8][2];
            #pragma unroll
            for (int mt = 0; mt < 4; mt++)
                ldsm_x4(af[mt][0], af[mt][1], af[mt][2], af[mt][3],
                        stOff + aRow[mt] + acol[kk]);
            #pragma unroll
            for (int nt2 = 0; nt2 < 4; nt2++) {
                uint32_t r0, r1, r2, r3;
                ldsm_x4(r0, r1, r2, r3, stOff + GTILE + bRow[nt2] + bcol[kk]);
                bf[nt2*2][0] = r0; bf[nt2*2][1] = r1;
                bf[nt2*2+1][0] = r2; bf[nt2*2+1][1] = r3;
            }
            #pragma unroll
            for (int mt = 0; mt < 4; mt++)
                #pragma unroll
                for (int nt = 0; nt < 8; nt++)
                    mma16816(acc[mt][nt], af[mt], bf[nt]);
        }
    }

    const int g = lane >> 2, t = lane & 3;
    #pragma unroll
    for (int mt = 0; mt < 4; mt++) {
        #pragma unroll
        for (int nt = 0; nt < 8; nt++) {
            const int col = colBase + wn * 64 + nt * 8 + t * 2;
            const float b0 = bias[col], b1 = bias[col + 1];
            const int row0 = rowBase + wm * 64 + mt * 16 + g;
            float v0 = acc[mt][nt][0] + b0, v1 = acc[mt][nt][1] + b1;
            float v2 = acc[mt][nt][2] + b0, v3 = acc[mt][nt][3] + b1;
            if (F16OUT) {
                *(uint32_t*)(Cf + (size_t)row0 * N + col)       = packhf(v0, v1);
                *(uint32_t*)(Cf + (size_t)(row0 + 8) * N + col) = packhf(v2, v3);
            } else {
                *(float2*)&C[(size_t)row0 * N + col]       = make_float2(v0, v1);
                *(float2*)&C[(size_t)(row0 + 8) * N + col] = make_float2(v2, v3);
            }
        }
    }
}

// ================= tensor-core causal flash attention (fp16, swizzled) =================
// R13 shape: 128 queries/CTA, 4 warps x 32 rows (2 m-frags/warp), K-tiles of 64,
// 3-stage ring. Adds a bit-identical softmax fast path: when the running max
// doesn't change, cr == 1.0 exactly and the O/l rescale is skipped.
#define TILEB 8192                    // 64 rows x 128B (SW128)
#define BUFB  (2*TILEB)               // K, V = 16384 B
#define ATT_SMEM (3*BUFB)             // 49152 B (buffer2 doubles as Q staging)
#define ESC 0.18033688f               // 0.125 * log2(e)

__global__ __launch_bounds__(128, 2)
void attn_mma(const __half* __restrict__ qkv, __half* __restrict__ yf)
{
    extern __shared__ __align__(16) char sm[];
    const uint32_t smBase = smem_u32(sm);

    const int tid  = threadIdx.x;
    const int lane = tid & 31;
    const int wm   = tid >> 5;          // 0..3, rows wm*32..wm*32+31
    const int bh = blockIdx.y;
    const int b  = bh / Hn;
    const int h  = bh % Hn;
    const int q0 = (gridDim.x - 1 - blockIdx.x) * 128;   // big tiles first

    const int mat = lane >> 3, r8 = lane & 7;
    const int g = lane >> 2, t = lane & 3;
    const uint32_t pat = (uint32_t)r8 << 4;

    const int nk = q0 / 64 + 2;

    // ---- stage Q into buffer2 region (1024 chunks / 128 threads) ----
    #pragma unroll
    for (int i = 0; i < 8; i++) {
        const int idx = tid + i * 128;
        const int r   = idx >> 3;
        const int c8  = idx & 7;
        const uint32_t dst = smBase + 2u*BUFB
                           + (uint32_t)(r * 128 + ((c8 * 16) ^ ((r & 7) << 4)));
        const __half* src = qkv + (size_t)(b * Tseq + q0 + r) * C3 + h * HD + c8 * 8;
        CP_ASYNC16(dst, src);
    }
    CP_COMMIT();

    uint32_t kRow[4], kcol[4], qcol[4], vcol[4];
    #pragma unroll
    for (int nt2 = 0; nt2 < 4; nt2++) {
        kRow[nt2] = (uint32_t)(nt2 * 16 + (mat >> 1) * 8 + r8) * 128;
        vcol[nt2] = (uint32_t)(nt2 * 32 + (mat >> 1) * 16) ^ pat;
    }
    #pragma unroll
    for (int ks = 0; ks < 4; ks++) {
        kcol[ks] = (uint32_t)(ks * 32 + (mat & 1) * 16) ^ pat;
        qcol[ks] = (uint32_t)(ks * 32 + (mat >> 1) * 16) ^ pat;
    }
    const uint32_t vRow = (uint32_t)((mat & 1) * 8 + r8) * 128;

    auto fill = [&](int it) {
        const int k0 = it * 64;
        const uint32_t bufOff = (uint32_t)(it % 3) * BUFB;
        #pragma unroll
        for (int i = 0; i < 8; i++) {
            const int idx = tid + i * 128;       // 1024 chunks
            const int tile = idx >> 9;           // 0 K, 1 V
            const int r    = (idx >> 3) & 63;
            const int c8   = idx & 7;
            const uint32_t dst = smBase + bufOff + (uint32_t)tile * TILEB
                               + (uint32_t)(r * 128 + ((c8 * 16) ^ ((r & 7) << 4)));
            const __half* src = qkv + (size_t)(b * Tseq + k0 + r) * C3 + h * HD + c8 * 8
                              + (tile ? 2 * Cdim : Cdim);
            CP_ASYNC16(dst, src);
        }
        CP_COMMIT();
    };

    fill(0);
    fill(1);

    CP_WAIT(2);
    __syncthreads();

    uint32_t qf[2][4][4];
    #pragma unroll
    for (int mt = 0; mt < 2; mt++) {
        const uint32_t qRow = (uint32_t)(wm * 32 + mt * 16 + (mat & 1) * 8 + r8) * 128;
        #pragma unroll
        for (int ks = 0; ks < 4; ks++)
            ldsm_x4(qf[mt][ks][0], qf[mt][ks][1], qf[mt][ks][2], qf[mt][ks][3],
                    smBase + 2u*BUFB + qRow + qcol[ks]);
    }

    float O[2][8][4];
    #pragma unroll
    for (int mt = 0; mt < 2; mt++)
        #pragma unroll
        for (int nt = 0; nt < 8; nt++)
            #pragma unroll
            for (int q = 0; q < 4; q++) O[mt][nt][q] = 0.f;
    float mm[2][2], ll[2][2];
    #pragma unroll
    for (int mt = 0; mt < 2; mt++) { mm[mt][0] = mm[mt][1] = -1e30f; ll[mt][0] = ll[mt][1] = 0.f; }

    const uint32_t onesb[2] = {0x3C003C00u, 0x3C003C00u};   // fp16 1.0 x4

    for (int it = 0; it < nk; ++it) {
        if (it < nk - 1) { CP_WAIT(1); } else { CP_WAIT(0); }
        __syncthreads();
        if (it + 2 < nk) fill(it + 2);

        const int k0 = it * 64;
        const uint32_t bufO = smBase + (uint32_t)(it % 3) * BUFB;

        // ---- S = Qf·Kf^T (both m-frags share each K fragment) ----
        float S[2][8][4];
        #pragma unroll
        for (int mt = 0; mt < 2; mt++)
            #pragma unroll
            for (int nt = 0; nt < 8; nt++)
                #pragma unroll
                for (int q = 0; q < 4; q++) S[mt][nt][q] = 0.f;

        #pragma unroll
        for (int ks = 0; ks < 4; ks++) {
            uint32_t kf[8][2];
            #pragma unroll
            for (int nt2 = 0; nt2 < 4; nt2++) {
                uint32_t r0, r1, r2, r3;
                ldsm_x4(r0, r1, r2, r3, bufO + kRow[nt2] + kcol[ks]);
                kf[nt2*2][0] = r0; kf[nt2*2][1] = r1;
                kf[nt2*2+1][0] = r2; kf[nt2*2+1][1] = r3;
            }
            #pragma unroll
            for (int mt = 0; mt < 2; mt++)
                #pragma unroll
                for (int nt = 0; nt < 8; nt++)
                    mma16816(S[mt][nt], qf[mt][ks], kf[nt]);
        }

        // ---- causal mask (diagonal tiles only) ----
        if (k0 + 63 > q0 + wm * 32) {
            #pragma unroll
            for (int mt = 0; mt < 2; mt++) {
                const int rg0 = q0 + wm * 32 + mt * 16 + g;
                const int rg1 = rg0 + 8;
                #pragma unroll
                for (int nt = 0; nt < 8; nt++) {
                    const int c = k0 + nt * 8 + t * 2;
                    if (c     > rg0) S[mt][nt][0] = -1e30f;
                    if (c + 1 > rg0) S[mt][nt][1] = -1e30f;
                    if (c     > rg1) S[mt][nt][2] = -1e30f;
                    if (c + 1 > rg1) S[mt][nt][3] = -1e30f;
                }
            }
        }

        // ---- online softmax + P fragments (per m-frag) ----
        uint32_t pf[2][4][4];
        #pragma unroll
        for (int mt = 0; mt < 2; mt++) {
            float mx0 = -1e30f, mx1 = -1e30f;
            #pragma unroll
            for (int nt = 0; nt < 8; nt++) {
                mx0 = fmaxf(mx0, fmaxf(S[mt][nt][0], S[mt][nt][1]));
                mx1 = fmaxf(mx1, fmaxf(S[mt][nt][2], S[mt][nt][3]));
            }
            mx0 = fmaxf(mx0, __shfl_xor_sync(0xffffffffu, mx0, 1));
            mx0 = fmaxf(mx0, __shfl_xor_sync(0xffffffffu, mx0, 2));
            mx1 = fmaxf(mx1, __shfl_xor_sync(0xffffffffu, mx1, 1));
            mx1 = fmaxf(mx1, __shfl_xor_sync(0xffffffffu, mx1, 2));

            float cr0 = 1.f, cr1 = 1.f;
            // fast path: max unchanged -> cr == 1.0 exactly; skip rescale (bit-identical)
            if (mx0 > mm[mt][0] || mx1 > mm[mt][1]) {
                const float mn0 = fmaxf(mm[mt][0], mx0);
                const float mn1 = fmaxf(mm[mt][1], mx1);
                cr0 = exp2f((mm[mt][0] - mn0) * ESC);
                cr1 = exp2f((mm[mt][1] - mn1) * ESC);
                mm[mt][0] = mn0; mm[mt][1] = mn1;
                #pragma unroll
                for (int nt = 0; nt < 8; nt++) {
                    O[mt][nt][0] *= cr0; O[mt][nt][1] *= cr0;
                    O[mt][nt][2] *= cr1; O[mt][nt][3] *= cr1;
                }
            }

            const float nE0 = mm[mt][0] * ESC, nE1 = mm[mt][1] * ESC;
            #pragma unroll
            for (int kk = 0; kk < 4; kk++) {
                pf[mt][kk][0] = ex2_f16x2(packhf(fmaf(S[mt][2*kk][0],   ESC, -nE0), fmaf(S[mt][2*kk][1],   ESC, -nE0)));
                pf[mt][kk][1] = ex2_f16x2(packhf(fmaf(S[mt][2*kk][2],   ESC, -nE1), fmaf(S[mt][2*kk][3],   ESC, -nE1)));
                pf[mt][kk][2] = ex2_f16x2(packhf(fmaf(S[mt][2*kk+1][0], ESC, -nE0), fmaf(S[mt][2*kk+1][1], ESC, -nE0)));
                pf[mt][kk][3] = ex2_f16x2(packhf(fmaf(S[mt][2*kk+1][2], ESC, -nE1), fmaf(S[mt][2*kk+1][3], ESC, -nE1)));
            }

            float lac[4] = {0.f, 0.f, 0.f, 0.f};
            #pragma unroll
            for (int kk = 0; kk < 4; kk++) mma16816(lac, pf[mt][kk], onesb);
            ll[mt][0] = ll[mt][0] * cr0 + lac[0];
            ll[mt][1] = ll[mt][1] * cr1 + lac[2];
        }

        // ---- O += Pf·Vf (both m-frags share each V fragment) ----
        #pragma unroll
        for (int kk = 0; kk < 4; kk++) {
            uint32_t vf[8][2];
            #pragma unroll
            for (int nd2 = 0; nd2 < 4; nd2++) {
                uint32_t r0, r1, r2, r3;
                ldsm_x4_t(r0, r1, r2, r3, bufO + TILEB + vRow + kk * 2048 + vcol[nd2]);
                vf[nd2*2][0] = r0; vf[nd2*2][1] = r1;
                vf[nd2*2+1][0] = r2; vf[nd2*2+1][1] = r3;
            }
            #pragma unroll
            for (int mt = 0; mt < 2; mt++)
                #pragma unroll
                for (int nd = 0; nd < 8; nd++)
                    mma16816(O[mt][nd], pf[mt][kk], vf[nd]);
        }
    }

    // ---- epilogue: normalize, round to fp16, store ----
    #pragma unroll
    for (int mt = 0; mt < 2; mt++) {
        const float i0 = 1.f / ll[mt][0], i1 = 1.f / ll[mt][1];
        const int rg0 = q0 + wm * 32 + mt * 16 + g;
        const size_t base0 = (size_t)(b * Tseq + rg0) * Cdim + h * HD;
        const size_t base1 = (size_t)(b * Tseq + rg0 + 8) * Cdim + h * HD;
        #pragma unroll
        for (int nt = 0; nt < 8; nt++) {
            const int col = nt * 8 + t * 2;
            *(uint32_t*)(yf + base0 + col) = packhf(O[mt][nt][0] * i0, O[mt][nt][1] * i0);
            *(uint32_t*)(yf + base1 + col) = packhf(O[mt][nt][2] * i1, O[mt][nt][3] * i1);
        }
    }
}

// ---------------- launch ----------------
extern "C" void kernel_launch(void* const* d_in, const int* in_sizes, int n_in,
                              void* d_out, int out_size)
{
    const float* x     = (const float*)d_in[0];
    const float* qkv_w = (const float*)d_in[1];
    const float* qkv_b = (const float*)d_in[2];
    const float* out_w = (const float*)d_in[3];
    const float* out_b = (const float*)d_in[4];
    float* out = (float*)d_out;

    __half *xf, *qkvf, *yf, *wqf, *wof;
    cudaGetSymbolAddress((void**)&xf,   g_xf);
    cudaGetSymbolAddress((void**)&qkvf, g_qkvf);
    cudaGetSymbolAddress((void**)&yf,   g_yf);
    cudaGetSymbolAddress((void**)&wqf,  g_wqf);
    cudaGetSymbolAddress((void**)&wof,  g_wof);

    cudaFuncSetAttribute(gemm_mma<true>,  cudaFuncAttributeMaxDynamicSharedMemorySize, GEMM_SMEM);
    cudaFuncSetAttribute(gemm_mma<false>, cudaFuncAttributeMaxDynamicSharedMemorySize, GEMM_SMEM);
    cudaFuncSetAttribute(attn_mma, cudaFuncAttributeMaxDynamicSharedMemorySize, ATT_SMEM);

    const int M = Mrows;   // 8192

    // 0) fused prep
    prep_kernel<<<XB + WQB + WOB, 256>>>(x, xf, qkv_w, wqf, out_w, wof);

    // 1) QKV projection -> fp16 qkv
    gemm_mma<true><<<dim3(C3 / GBN, M / GBM), 128, GEMM_SMEM>>>(
        xf, wqf, qkv_b, nullptr, qkvf, M, C3, Cdim);

    // 2) causal attention -> fp16 y
    attn_mma<<<dim3(Tseq / 128, Bsz * Hn), 128, ATT_SMEM>>>(qkvf, yf);

    // 3) output projection -> fp32 out
    gemm_mma<false><<<dim3(Cdim / GBN, M / GBM), 128, GEMM_SMEM>>>(
        yf, wof, out_b, out, nullptr, M, Cdim, Cdim);
}

// round 16
// speedup vs baseline: 1.0608x; 1.0416x over previous
#include <cuda_runtime.h>
#include <cuda_fp16.h>
#include <cstdint>
#include <math.h>

#define Bsz 2
#define Tseq 4096
#define Cdim 768
#define Hn 12
#define HD 64
#define C3 (3*Cdim)
#define Mrows (Bsz*Tseq)   // 8192

// ---------------- scratch (no allocs allowed) ----------------
__device__ __align__(16) __half g_xf  [(size_t)Mrows * Cdim];
__device__ __align__(16) __half g_qkvf[(size_t)Mrows * C3];
__device__ __align__(16) __half g_yf  [(size_t)Mrows * Cdim];
__device__ __align__(16) __half g_wqf [(size_t)C3 * Cdim];   // qkv_w^T  [N,K] fp16
__device__ __align__(16) __half g_wof [(size_t)Cdim * Cdim]; // out_w^T  [N,K] fp16

// ================= portable PTX helpers =================
__device__ __forceinline__ uint32_t smem_u32(const void* p) {
    uint32_t a;
    asm("{ .reg .u64 t; cvta.to.shared.u64 t, %1; cvt.u32.u64 %0, t; }" : "=r"(a) : "l"(p));
    return a;
}
#define CP_ASYNC16(dst, src) \
    asm volatile("cp.async.cg.shared.global [%0], [%1], 16;" :: "r"(dst), "l"(src) : "memory")
#define CP_COMMIT() asm volatile("cp.async.commit_group;" ::: "memory")
#define CP_WAIT(n)  asm volatile("cp.async.wait_group %0;" :: "n"(n) : "memory")

__device__ __forceinline__ void ldsm_x4(uint32_t& r0, uint32_t& r1, uint32_t& r2, uint32_t& r3,
                                        uint32_t addr) {
    asm volatile("ldmatrix.sync.aligned.m8n8.x4.shared.b16 {%0,%1,%2,%3}, [%4];"
                 : "=r"(r0), "=r"(r1), "=r"(r2), "=r"(r3) : "r"(addr));
}
__device__ __forceinline__ void ldsm_x4_t(uint32_t& r0, uint32_t& r1, uint32_t& r2, uint32_t& r3,
                                          uint32_t addr) {
    asm volatile("ldmatrix.sync.aligned.m8n8.x4.trans.shared.b16 {%0,%1,%2,%3}, [%4];"
                 : "=r"(r0), "=r"(r1), "=r"(r2), "=r"(r3) : "r"(addr));
}
__device__ __forceinline__ void mma16816(float* d, const uint32_t* a, const uint32_t* b) {
    asm volatile(
        "mma.sync.aligned.m16n8k16.row.col.f32.f16.f16.f32 "
        "{%0,%1,%2,%3}, {%4,%5,%6,%7}, {%8,%9}, {%0,%1,%2,%3};"
        : "+f"(d[0]), "+f"(d[1]), "+f"(d[2]), "+f"(d[3])
        : "r"(a[0]), "r"(a[1]), "r"(a[2]), "r"(a[3]), "r"(b[0]), "r"(b[1]));
}
__device__ __forceinline__ uint32_t packhf(float lo, float hi) {
    uint32_t d;
    asm("cvt.rn.f16x2.f32 %0, %1, %2;" : "=r"(d) : "f"(hi), "f"(lo));
    return d;
}
__device__ __forceinline__ uint32_t ex2_f16x2(uint32_t a) {
    uint32_t d;
    asm("ex2.approx.f16x2 %0, %1;" : "=r"(d) : "r"(a));
    return d;
}

// ================= fused prep: round x + round-transpose both weights =================
#define XB  ((Mrows*Cdim/4 + 255)/256)   // 6144
#define WQB ((C3/32)*(Cdim/32))          // 1728
#define WOB ((Cdim/32)*(Cdim/32))        // 576

__global__ __launch_bounds__(256)
void prep_kernel(const float* __restrict__ x, __half* __restrict__ xf,
                 const float* __restrict__ wq, __half* __restrict__ wqf,
                 const float* __restrict__ wo, __half* __restrict__ wof)
{
    const int bid = blockIdx.x;
    if (bid < XB) {
        int i4 = bid * 256 + threadIdx.x;
        if (i4 >= Mrows * Cdim / 4) return;
        float4 v = ((const float4*)x)[i4];
        uint2 o;
        o.x = packhf(v.x, v.y);
        o.y = packhf(v.z, v.w);
        ((uint2*)xf)[i4] = o;
        return;
    }
    const float* W; __half* Tf; int K, N, bx, by;
    if (bid < XB + WQB) {
        int j = bid - XB;
        W = wq; Tf = wqf; K = Cdim; N = C3;
        bx = j % (C3/32); by = j / (C3/32);
    } else {
        int j = bid - XB - WQB;
        W = wo; Tf = wof; K = Cdim; N = Cdim;
        bx = j % (Cdim/32); by = j / (Cdim/32);
    }
    __shared__ float t[32][33];
    const int n0 = bx * 32, k0 = by * 32;
    const int tx = threadIdx.x & 31, ty = (threadIdx.x >> 5);
    #pragma unroll
    for (int j = 0; j < 4; j++)
        t[ty + j*8][tx] = W[(size_t)(k0 + ty + j*8) * N + n0 + tx];
    __syncthreads();
    #pragma unroll
    for (int j = 0; j < 4; j++)
        Tf[(size_t)(n0 + ty + j*8) * K + k0 + tx] = __float2half_rn(t[tx][ty + j*8]);
}

// ================= warp-MMA fp16 GEMM (swizzled, K-step 64, 3-stage ring) =================
// BM x 128 block tile, 4 warps (2m x 2n), warp tile (BM/2) x 64.
// BM=128: 2 CTAs/SM (regs ~250). BM=64: 3 CTAs/SM (regs ~130) — finer wave granularity.
#define GBN 128
#define GBK 64

template<int BM, bool F16OUT>
__global__ __launch_bounds__(128, (BM == 128 ? 2 : 3))
void gemm_mma(const __half* __restrict__ Af, const __half* __restrict__ Bf,
              const float* __restrict__ bias, float* __restrict__ C,
              __half* __restrict__ Cf,
              int M, int N, int K)
{
    constexpr int FR = BM / 32;                 // m-frags per warp
    constexpr uint32_t GTILE_A = (uint32_t)BM * 128;   // A tile bytes
    constexpr uint32_t GTILE_B = 16384;                // B tile bytes (128 rows)
    constexpr uint32_t GSTAGE  = GTILE_A + GTILE_B;
    constexpr int ACH = BM * 8;                 // A chunks per stage
    constexpr int NCH = (BM + 128) * 8;         // total chunks per stage

    extern __shared__ __align__(16) char gsm[];
    const uint32_t smBase = smem_u32(gsm);

    const int tid  = threadIdx.x;
    const int lane = tid & 31;
    const int wid  = tid >> 5;        // 0..3
    const int wm   = wid & 1;
    const int wn   = wid >> 1;
    const int rowBase = blockIdx.y * BM;
    const int colBase = blockIdx.x * GBN;

    const int mat = lane >> 3, r8 = lane & 7;
    const uint32_t pat = (uint32_t)r8 << 4;

    uint32_t aRow[FR], bRow[4], acol[4], bcol[4];
    #pragma unroll
    for (int mt = 0; mt < FR; mt++)
        aRow[mt] = (uint32_t)(wm * (BM/2) + mt * 16 + (mat & 1) * 8 + r8) * 128;
    #pragma unroll
    for (int nt2 = 0; nt2 < 4; nt2++)
        bRow[nt2] = (uint32_t)(wn * 64 + nt2 * 16 + (mat >> 1) * 8 + r8) * 128;
    #pragma unroll
    for (int kk = 0; kk < 4; kk++) {
        acol[kk] = (uint32_t)(kk * 32 + (mat >> 1) * 16) ^ pat;
        bcol[kk] = (uint32_t)(kk * 32 + (mat & 1) * 16) ^ pat;
    }

    float acc[FR][8][4];
    #pragma unroll
    for (int i = 0; i < FR; i++)
        #pragma unroll
        for (int j = 0; j < 8; j++)
            #pragma unroll
            for (int q = 0; q < 4; q++) acc[i][j][q] = 0.f;

    const int KC = K / GBK;   // 12

    auto issue_tile = [&](int it) {
        const uint32_t stOff = (uint32_t)(it % 3) * GSTAGE;
        const int kc = it;
        #pragma unroll
        for (int i = 0; i < NCH / 128; i++) {
            const int idx = tid + i * 128;
            const int c8  = idx & 7;
            uint32_t dst;
            const __half* src;
            if (idx < ACH) {
                const int r = idx >> 3;
                dst = smBase + stOff
                    + (uint32_t)(r * 128 + ((c8 * 16) ^ ((r & 7) << 4)));
                src = Af + (size_t)(rowBase + r) * K + kc * GBK + c8 * 8;
            } else {
                const int r = (idx - ACH) >> 3;
                dst = smBase + stOff + GTILE_A
                    + (uint32_t)(r * 128 + ((c8 * 16) ^ ((r & 7) << 4)));
                src = Bf + (size_t)(colBase + r) * K + kc * GBK + c8 * 8;
            }
            CP_ASYNC16(dst, src);
        }
        CP_COMMIT();
    };

    issue_tile(0);
    issue_tile(1);

    for (int it = 0; it < KC; ++it) {
        if (it + 1 < KC) { CP_WAIT(1); } else { CP_WAIT(0); }
        __syncthreads();
        if (it + 2 < KC) issue_tile(it + 2);

        const uint32_t stOff = smBase + (uint32_t)(it % 3) * GSTAGE;
        #pragma unroll
        for (int kk = 0; kk < 4; kk++) {
            uint32_t af[FR][4], bf[8][2];
            #pragma unroll
            for (int mt = 0; mt < FR; mt++)
                ldsm_x4(af[mt][0], af[mt][1], af[mt][2], af[mt][3],
                        stOff + aRow[mt] + acol[kk]);
            #pragma unroll
            for (int nt2 = 0; nt2 < 4; nt2++) {
                uint32_t r0, r1, r2, r3;
                ldsm_x4(r0, r1, r2, r3, stOff + GTILE_A + bRow[nt2] + bcol[kk]);
                bf[nt2*2][0] = r0; bf[nt2*2][1] = r1;
                bf[nt2*2+1][0] = r2; bf[nt2*2+1][1] = r3;
            }
            #pragma unroll
            for (int mt = 0; mt < FR; mt++)
                #pragma unroll
                for (int nt = 0; nt < 8; nt++)
                    mma16816(acc[mt][nt], af[mt], bf[nt]);
        }
    }

    const int g = lane >> 2, t = lane & 3;
    #pragma unroll
    for (int mt = 0; mt < FR; mt++) {
        #pragma unroll
        for (int nt = 0; nt < 8; nt++) {
            const int col = colBase + wn * 64 + nt * 8 + t * 2;
            const float b0 = bias[col], b1 = bias[col + 1];
            const int row0 = rowBase + wm * (BM/2) + mt * 16 + g;
            float v0 = acc[mt][nt][0] + b0, v1 = acc[mt][nt][1] + b1;
            float v2 = acc[mt][nt][2] + b0, v3 = acc[mt][nt][3] + b1;
            if (F16OUT) {
                *(uint32_t*)(Cf + (size_t)row0 * N + col)       = packhf(v0, v1);
                *(uint32_t*)(Cf + (size_t)(row0 + 8) * N + col) = packhf(v2, v3);
            } else {
                *(float2*)&C[(size_t)row0 * N + col]       = make_float2(v0, v1);
                *(float2*)&C[(size_t)(row0 + 8) * N + col] = make_float2(v2, v3);
            }
        }
    }
}

#define GEMM_SMEM_128 (3*(128*128 + 16384))   // 98304
#define GEMM_SMEM_64  (3*(64*128 + 16384))    // 73728

// ================= tensor-core causal flash attention (fp16, swizzled) =================
// R13 shape: 128 queries/CTA, 4 warps x 32 rows (2 m-frags/warp), K-tiles of 64,
// 3-stage ring, exp via ex2.approx.f16x2, row-sums via ones-MMA.
#define TILEB 8192                    // 64 rows x 128B (SW128)
#define BUFB  (2*TILEB)               // K, V = 16384 B
#define ATT_SMEM (3*BUFB)             // 49152 B (buffer2 doubles as Q staging)
#define ESC 0.18033688f               // 0.125 * log2(e)

__global__ __launch_bounds__(128, 2)
void attn_mma(const __half* __restrict__ qkv, __half* __restrict__ yf)
{
    extern __shared__ __align__(16) char sm[];
    const uint32_t smBase = smem_u32(sm);

    const int tid  = threadIdx.x;
    const int lane = tid & 31;
    const int wm   = tid >> 5;          // 0..3, rows wm*32..wm*32+31
    const int bh = blockIdx.y;
    const int b  = bh / Hn;
    const int h  = bh % Hn;
    const int q0 = (gridDim.x - 1 - blockIdx.x) * 128;   // big tiles first

    const int mat = lane >> 3, r8 = lane & 7;
    const int g = lane >> 2, t = lane & 3;
    const uint32_t pat = (uint32_t)r8 << 4;

    const int nk = q0 / 64 + 2;

    // ---- stage Q into buffer2 region (1024 chunks / 128 threads) ----
    #pragma unroll
    for (int i = 0; i < 8; i++) {
        const int idx = tid + i * 128;
        const int r   = idx >> 3;
        const int c8  = idx & 7;
        const uint32_t dst = smBase + 2u*BUFB
                           + (uint32_t)(r * 128 + ((c8 * 16) ^ ((r & 7) << 4)));
        const __half* src = qkv + (size_t)(b * Tseq + q0 + r) * C3 + h * HD + c8 * 8;
        CP_ASYNC16(dst, src);
    }
    CP_COMMIT();

    uint32_t kRow[4], kcol[4], qcol[4], vcol[4];
    #pragma unroll
    for (int nt2 = 0; nt2 < 4; nt2++) {
        kRow[nt2] = (uint32_t)(nt2 * 16 + (mat >> 1) * 8 + r8) * 128;
        vcol[nt2] = (uint32_t)(nt2 * 32 + (mat >> 1) * 16) ^ pat;
    }
    #pragma unroll
    for (int ks = 0; ks < 4; ks++) {
        kcol[ks] = (uint32_t)(ks * 32 + (mat & 1) * 16) ^ pat;
        qcol[ks] = (uint32_t)(ks * 32 + (mat >> 1) * 16) ^ pat;
    }
    const uint32_t vRow = (uint32_t)((mat & 1) * 8 + r8) * 128;

    auto fill = [&](int it) {
        const int k0 = it * 64;
        const uint32_t bufOff = (uint32_t)(it % 3) * BUFB;
        #pragma unroll
        for (int i = 0; i < 8; i++) {
            const int idx = tid + i * 128;       // 1024 chunks
            const int tile = idx >> 9;           // 0 K, 1 V
            const int r    = (idx >> 3) & 63;
            const int c8   = idx & 7;
            const uint32_t dst = smBase + bufOff + (uint32_t)tile * TILEB
                               + (uint32_t)(r * 128 + ((c8 * 16) ^ ((r & 7) << 4)));
            const __half* src = qkv + (size_t)(b * Tseq + k0 + r) * C3 + h * HD + c8 * 8
                              + (tile ? 2 * Cdim : Cdim);
            CP_ASYNC16(dst, src);
        }
        CP_COMMIT();
    };

    fill(0);
    fill(1);

    CP_WAIT(2);
    __syncthreads();

    uint32_t qf[2][4][4];
    #pragma unroll
    for (int mt = 0; mt < 2; mt++) {
        const uint32_t qRow = (uint32_t)(wm * 32 + mt * 16 + (mat & 1) * 8 + r8) * 128;
        #pragma unroll
        for (int ks = 0; ks < 4; ks++)
            ldsm_x4(qf[mt][ks][0], qf[mt][ks][1], qf[mt][ks][2], qf[mt][ks][3],
                    smBase + 2u*BUFB + qRow + qcol[ks]);
    }

    float O[2][8][4];
    #pragma unroll
    for (int mt = 0; mt < 2; mt++)
        #pragma unroll
        for (int nt = 0; nt < 8; nt++)
            #pragma unroll
            for (int q = 0; q < 4; q++) O[mt][nt][q] = 0.f;
    float mm[2][2], ll[2][2];
    #pragma unroll
    for (int mt = 0; mt < 2; mt++) { mm[mt][0] = mm[mt][1] = -1e30f; ll[mt][0] = ll[mt][1] = 0.f; }

    const uint32_t onesb[2] = {0x3C003C00u, 0x3C003C00u};   // fp16 1.0 x4

    for (int it = 0; it < nk; ++it) {
        if (it < nk - 1) { CP_WAIT(1); } else { CP_WAIT(0); }
        __syncthreads();
        if (it + 2 < nk) fill(it + 2);

        const int k0 = it * 64;
        const uint32_t bufO = smBase + (uint32_t)(it % 3) * BUFB;

        // ---- S = Qf·Kf^T (both m-frags share each K fragment) ----
        float S[2][8][4];
        #pragma unroll
        for (int mt = 0; mt < 2; mt++)
            #pragma unroll
            for (int nt = 0; nt < 8; nt++)
                #pragma unroll
                for (int q = 0; q < 4; q++) S[mt][nt][q] = 0.f;

        #pragma unroll
        for (int ks = 0; ks < 4; ks++) {
            uint32_t kf[8][2];
            #pragma unroll
            for (int nt2 = 0; nt2 < 4; nt2++) {
                uint32_t r0, r1, r2, r3;
                ldsm_x4(r0, r1, r2, r3, bufO + kRow[nt2] + kcol[ks]);
                kf[nt2*2][0] = r0; kf[nt2*2][1] = r1;
                kf[nt2*2+1][0] = r2; kf[nt2*2+1][1] = r3;
            }
            #pragma unroll
            for (int mt = 0; mt < 2; mt++)
                #pragma unroll
                for (int nt = 0; nt < 8; nt++)
                    mma16816(S[mt][nt], qf[mt][ks], kf[nt]);
        }

        // ---- causal mask (diagonal tiles only) ----
        if (k0 + 63 > q0 + wm * 32) {
            #pragma unroll
            for (int mt = 0; mt < 2; mt++) {
                const int rg0 = q0 + wm * 32 + mt * 16 + g;
                const int rg1 = rg0 + 8;
                #pragma unroll
                for (int nt = 0; nt < 8; nt++) {
                    const int c = k0 + nt * 8 + t * 2;
                    if (c     > rg0) S[mt][nt][0] = -1e30f;
                    if (c + 1 > rg0) S[mt][nt][1] = -1e30f;
                    if (c     > rg1) S[mt][nt][2] = -1e30f;
                    if (c + 1 > rg1) S[mt][nt][3] = -1e30f;
                }
            }
        }

        // ---- online softmax + P fragments (per m-frag) ----
        uint32_t pf[2][4][4];
        #pragma unroll
        for (int mt = 0; mt < 2; mt++) {
            float mx0 = -1e30f, mx1 = -1e30f;
            #pragma unroll
            for (int nt = 0; nt < 8; nt++) {
                mx0 = fmaxf(mx0, fmaxf(S[mt][nt][0], S[mt][nt][1]));
                mx1 = fmaxf(mx1, fmaxf(S[mt][nt][2], S[mt][nt][3]));
            }
            mx0 = fmaxf(mx0, __shfl_xor_sync(0xffffffffu, mx0, 1));
            mx0 = fmaxf(mx0, __shfl_xor_sync(0xffffffffu, mx0, 2));
            mx1 = fmaxf(mx1, __shfl_xor_sync(0xffffffffu, mx1, 1));
            mx1 = fmaxf(mx1, __shfl_xor_sync(0xffffffffu, mx1, 2));

            const float mn0 = fmaxf(mm[mt][0], mx0);
            const float mn1 = fmaxf(mm[mt][1], mx1);
            const float cr0 = exp2f((mm[mt][0] - mn0) * ESC);
            const float cr1 = exp2f((mm[mt][1] - mn1) * ESC);
            mm[mt][0] = mn0; mm[mt][1] = mn1;
            #pragma unroll
            for (int nt = 0; nt < 8; nt++) {
                O[mt][nt][0] *= cr0; O[mt][nt][1] *= cr0;
                O[mt][nt][2] *= cr1; O[mt][nt][3] *= cr1;
            }

            const float nE0 = mn0 * ESC, nE1 = mn1 * ESC;
            #pragma unroll
            for (int kk = 0; kk < 4; kk++) {
                pf[mt][kk][0] = ex2_f16x2(packhf(fmaf(S[mt][2*kk][0],   ESC, -nE0), fmaf(S[mt][2*kk][1],   ESC, -nE0)));
                pf[mt][kk][1] = ex2_f16x2(packhf(fmaf(S[mt][2*kk][2],   ESC, -nE1), fmaf(S[mt][2*kk][3],   ESC, -nE1)));
                pf[mt][kk][2] = ex2_f16x2(packhf(fmaf(S[mt][2*kk+1][0], ESC, -nE0), fmaf(S[mt][2*kk+1][1], ESC, -nE0)));
                pf[mt][kk][3] = ex2_f16x2(packhf(fmaf(S[mt][2*kk+1][2], ESC, -nE1), fmaf(S[mt][2*kk+1][3], ESC, -nE1)));
            }

            float lac[4] = {0.f, 0.f, 0.f, 0.f};
            #pragma unroll
            for (int kk = 0; kk < 4; kk++) mma16816(lac, pf[mt][kk], onesb);
            ll[mt][0] = ll[mt][0] * cr0 + lac[0];
            ll[mt][1] = ll[mt][1] * cr1 + lac[2];
        }

        // ---- O += Pf·Vf (both m-frags share each V fragment) ----
        #pragma unroll
        for (int kk = 0; kk < 4; kk++) {
            uint32_t vf[8][2];
            #pragma unroll
            for (int nd2 = 0; nd2 < 4; nd2++) {
                uint32_t r0, r1, r2, r3;
                ldsm_x4_t(r0, r1, r2, r3, bufO + TILEB + vRow + kk * 2048 + vcol[nd2]);
                vf[nd2*2][0] = r0; vf[nd2*2][1] = r1;
                vf[nd2*2+1][0] = r2; vf[nd2*2+1][1] = r3;
            }
            #pragma unroll
            for (int mt = 0; mt < 2; mt++)
                #pragma unroll
                for (int nd = 0; nd < 8; nd++)
                    mma16816(O[mt][nd], pf[mt][kk], vf[nd]);
        }
    }

    // ---- epilogue: normalize, round to fp16, store ----
    #pragma unroll
    for (int mt = 0; mt < 2; mt++) {
        const float i0 = 1.f / ll[mt][0], i1 = 1.f / ll[mt][1];
        const int rg0 = q0 + wm * 32 + mt * 16 + g;
        const size_t base0 = (size_t)(b * Tseq + rg0) * Cdim + h * HD;
        const size_t base1 = (size_t)(b * Tseq + rg0 + 8) * Cdim + h * HD;
        #pragma unroll
        for (int nt = 0; nt < 8; nt++) {
            const int col = nt * 8 + t * 2;
            *(uint32_t*)(yf + base0 + col) = packhf(O[mt][nt][0] * i0, O[mt][nt][1] * i0);
            *(uint32_t*)(yf + base1 + col) = packhf(O[mt][nt][2] * i1, O[mt][nt][3] * i1);
        }
    }
}

// ---------------- launch ----------------
extern "C" void kernel_launch(void* const* d_in, const int* in_sizes, int n_in,
                              void* d_out, int out_size)
{
    const float* x     = (const float*)d_in[0];
    const float* qkv_w = (const float*)d_in[1];
    const float* qkv_b = (const float*)d_in[2];
    const float* out_w = (const float*)d_in[3];
    const float* out_b = (const float*)d_in[4];
    float* out = (float*)d_out;

    __half *xf, *qkvf, *yf, *wqf, *wof;
    cudaGetSymbolAddress((void**)&xf,   g_xf);
    cudaGetSymbolAddress((void**)&qkvf, g_qkvf);
    cudaGetSymbolAddress((void**)&yf,   g_yf);
    cudaGetSymbolAddress((void**)&wqf,  g_wqf);
    cudaGetSymbolAddress((void**)&wof,  g_wof);

    cudaFuncSetAttribute(gemm_mma<128, true>, cudaFuncAttributeMaxDynamicSharedMemorySize, GEMM_SMEM_128);
    cudaFuncSetAttribute(gemm_mma<64, false>, cudaFuncAttributeMaxDynamicSharedMemorySize, GEMM_SMEM_64);
    cudaFuncSetAttribute(attn_mma, cudaFuncAttributeMaxDynamicSharedMemorySize, ATT_SMEM);

    const int M = Mrows;   // 8192

    // 0) fused prep
    prep_kernel<<<XB + WQB + WOB, 256>>>(x, xf, qkv_w, wqf, out_w, wof);

    // 1) QKV projection -> fp16 qkv (128-row tiles, 2 CTAs/SM)
    gemm_mma<128, true><<<dim3(C3 / GBN, M / 128), 128, GEMM_SMEM_128>>>(
        xf, wqf, qkv_b, nullptr, qkvf, M, C3, Cdim);

    // 2) causal attention -> fp16 y (R13 form)
    attn_mma<<<dim3(Tseq / 128, Bsz * Hn), 128, ATT_SMEM>>>(qkvf, yf);

    // 3) output projection -> fp32 out (64-row tiles, 3 CTAs/SM, finer wave tail)
    gemm_mma<64, false><<<dim3(Cdim / GBN, M / 64), 128, GEMM_SMEM_64>>>(
        yf, wof, out_b, out, nullptr, M, Cdim, Cdim);
}

// round 17
// speedup vs baseline: 1.0685x; 1.0072x over previous
#include <cuda_runtime.h>
#include <cuda_fp16.h>
#include <cstdint>
#include <math.h>

#define Bsz 2
#define Tseq 4096
#define Cdim 768
#define Hn 12
#define HD 64
#define C3 (3*Cdim)
#define Mrows (Bsz*Tseq)   // 8192

// ---------------- scratch (no allocs allowed) ----------------
__device__ __align__(16) __half g_xf  [(size_t)Mrows * Cdim];
__device__ __align__(16) __half g_qkvf[(size_t)Mrows * C3];
__device__ __align__(16) __half g_yf  [(size_t)Mrows * Cdim];
__device__ __align__(16) __half g_wqf [(size_t)C3 * Cdim];   // qkv_w^T  [N,K] fp16
__device__ __align__(16) __half g_wof [(size_t)Cdim * Cdim]; // out_w^T  [N,K] fp16

// ================= portable PTX helpers =================
__device__ __forceinline__ uint32_t smem_u32(const void* p) {
    uint32_t a;
    asm("{ .reg .u64 t; cvta.to.shared.u64 t, %1; cvt.u32.u64 %0, t; }" : "=r"(a) : "l"(p));
    return a;
}
#define CP_ASYNC16(dst, src) \
    asm volatile("cp.async.cg.shared.global [%0], [%1], 16;" :: "r"(dst), "l"(src) : "memory")
#define CP_COMMIT() asm volatile("cp.async.commit_group;" ::: "memory")
#define CP_WAIT(n)  asm volatile("cp.async.wait_group %0;" :: "n"(n) : "memory")

__device__ __forceinline__ void ldsm_x4(uint32_t& r0, uint32_t& r1, uint32_t& r2, uint32_t& r3,
                                        uint32_t addr) {
    asm volatile("ldmatrix.sync.aligned.m8n8.x4.shared.b16 {%0,%1,%2,%3}, [%4];"
                 : "=r"(r0), "=r"(r1), "=r"(r2), "=r"(r3) : "r"(addr));
}
__device__ __forceinline__ void ldsm_x4_t(uint32_t& r0, uint32_t& r1, uint32_t& r2, uint32_t& r3,
                                          uint32_t addr) {
    asm volatile("ldmatrix.sync.aligned.m8n8.x4.trans.shared.b16 {%0,%1,%2,%3}, [%4];"
                 : "=r"(r0), "=r"(r1), "=r"(r2), "=r"(r3) : "r"(addr));
}
__device__ __forceinline__ void mma16816(float* d, const uint32_t* a, const uint32_t* b) {
    asm volatile(
        "mma.sync.aligned.m16n8k16.row.col.f32.f16.f16.f32 "
        "{%0,%1,%2,%3}, {%4,%5,%6,%7}, {%8,%9}, {%0,%1,%2,%3};"
        : "+f"(d[0]), "+f"(d[1]), "+f"(d[2]), "+f"(d[3])
        : "r"(a[0]), "r"(a[1]), "r"(a[2]), "r"(a[3]), "r"(b[0]), "r"(b[1]));
}
__device__ __forceinline__ uint32_t packhf(float lo, float hi) {
    uint32_t d;
    asm("cvt.rn.f16x2.f32 %0, %1, %2;" : "=r"(d) : "f"(hi), "f"(lo));
    return d;
}
__device__ __forceinline__ uint32_t ex2_f16x2(uint32_t a) {
    uint32_t d;
    asm("ex2.approx.f16x2 %0, %1;" : "=r"(d) : "r"(a));
    return d;
}

// ================= fused prep: round x + round-transpose both weights =================
#define XB  ((Mrows*Cdim/4 + 255)/256)   // 6144
#define WQB ((C3/32)*(Cdim/32))          // 1728
#define WOB ((Cdim/32)*(Cdim/32))        // 576

__global__ __launch_bounds__(256)
void prep_kernel(const float* __restrict__ x, __half* __restrict__ xf,
                 const float* __restrict__ wq, __half* __restrict__ wqf,
                 const float* __restrict__ wo, __half* __restrict__ wof)
{
    const int bid = blockIdx.x;
    if (bid < XB) {
        int i4 = bid * 256 + threadIdx.x;
        if (i4 >= Mrows * Cdim / 4) return;
        float4 v = ((const float4*)x)[i4];
        uint2 o;
        o.x = packhf(v.x, v.y);
        o.y = packhf(v.z, v.w);
        ((uint2*)xf)[i4] = o;
        return;
    }
    const float* W; __half* Tf; int K, N, bx, by;
    if (bid < XB + WQB) {
        int j = bid - XB;
        W = wq; Tf = wqf; K = Cdim; N = C3;
        bx = j % (C3/32); by = j / (C3/32);
    } else {
        int j = bid - XB - WQB;
        W = wo; Tf = wof; K = Cdim; N = Cdim;
        bx = j % (Cdim/32); by = j / (Cdim/32);
    }
    __shared__ float t[32][33];
    const int n0 = bx * 32, k0 = by * 32;
    const int tx = threadIdx.x & 31, ty = (threadIdx.x >> 5);
    #pragma unroll
    for (int j = 0; j < 4; j++)
        t[ty + j*8][tx] = W[(size_t)(k0 + ty + j*8) * N + n0 + tx];
    __syncthreads();
    #pragma unroll
    for (int j = 0; j < 4; j++)
        Tf[(size_t)(n0 + ty + j*8) * K + k0 + tx] = __float2half_rn(t[tx][ty + j*8]);
}

// ================= warp-MMA fp16 GEMM (swizzled, K-step 64, 3-stage ring) =================
// 128x128 block tile, 4 warps (2m x 2n), warp tile 64x64.
#define GBM 128
#define GBN 128
#define GBK 64
#define GTILE 16384              // 128 rows x 128B (SW128)
#define GSTAGE (2*GTILE)         // Af | Bf = 32768 B
#define GEMM_SMEM (3*GSTAGE)     // 98304 B

template<bool F16OUT>
__global__ __launch_bounds__(128, 2)
void gemm_mma(const __half* __restrict__ Af, const __half* __restrict__ Bf,
              const float* __restrict__ bias, float* __restrict__ C,
              __half* __restrict__ Cf,
              int M, int N, int K)
{
    extern __shared__ __align__(16) char gsm[];
    const uint32_t smBase = smem_u32(gsm);

    const int tid  = threadIdx.x;
    const int lane = tid & 31;
    const int wid  = tid >> 5;        // 0..3
    const int wm   = wid & 1;
    const int wn   = wid >> 1;
    const int rowBase = blockIdx.y * GBM;
    const int colBase = blockIdx.x * GBN;

    const int mat = lane >> 3, r8 = lane & 7;
    const uint32_t pat = (uint32_t)r8 << 4;

    uint32_t aRow[4], bRow[4], acol[4], bcol[4];
    #pragma unroll
    for (int mt = 0; mt < 4; mt++)
        aRow[mt] = (uint32_t)(wm * 64 + mt * 16 + (mat & 1) * 8 + r8) * 128;
    #pragma unroll
    for (int nt2 = 0; nt2 < 4; nt2++)
        bRow[nt2] = (uint32_t)(wn * 64 + nt2 * 16 + (mat >> 1) * 8 + r8) * 128;
    #pragma unroll
    for (int kk = 0; kk < 4; kk++) {
        acol[kk] = (uint32_t)(kk * 32 + (mat >> 1) * 16) ^ pat;
        bcol[kk] = (uint32_t)(kk * 32 + (mat & 1) * 16) ^ pat;
    }

    float acc[4][8][4];
    #pragma unroll
    for (int i = 0; i < 4; i++)
        #pragma unroll
        for (int j = 0; j < 8; j++)
            #pragma unroll
            for (int q = 0; q < 4; q++) acc[i][j][q] = 0.f;

    const int KC = K / GBK;   // 12

    auto issue_tile = [&](int it) {
        const uint32_t stOff = (uint32_t)(it % 3) * GSTAGE;
        const int kc = it;
        #pragma unroll
        for (int i = 0; i < 16; i++) {
            const int idx  = tid + i * 128;
            const int tile = idx >> 10;
            const int rem  = idx & 1023;
            const int r    = rem >> 3;
            const int c8   = rem & 7;
            const uint32_t dst = smBase + stOff + (uint32_t)tile * GTILE
                               + (uint32_t)(r * 128 + ((c8 * 16) ^ ((r & 7) << 4)));
            const __half* src = tile ? (Bf + (size_t)(colBase + r) * K + kc * GBK + c8 * 8)
                                     : (Af + (size_t)(rowBase + r) * K + kc * GBK + c8 * 8);
            CP_ASYNC16(dst, src);
        }
        CP_COMMIT();
    };

    issue_tile(0);
    issue_tile(1);

    for (int it = 0; it < KC; ++it) {
        if (it + 1 < KC) { CP_WAIT(1); } else { CP_WAIT(0); }
        __syncthreads();
        if (it + 2 < KC) issue_tile(it + 2);

        const uint32_t stOff = smBase + (uint32_t)(it % 3) * GSTAGE;
        #pragma unroll
        for (int kk = 0; kk < 4; kk++) {
            uint32_t af[4][4], bf[8][2];
            #pragma unroll
            for (int mt = 0; mt < 4; mt++)
                ldsm_x4(af[mt][0], af[mt][1], af[mt][2], af[mt][3],
                        stOff + aRow[mt] + acol[kk]);
            #pragma unroll
            for (int nt2 = 0; nt2 < 4; nt2++) {
                uint32_t r0, r1, r2, r3;
                ldsm_x4(r0, r1, r2, r3, stOff + GTILE + bRow[nt2] + bcol[kk]);
                bf[nt2*2][0] = r0; bf[nt2*2][1] = r1;
                bf[nt2*2+1][0] = r2; bf[nt2*2+1][1] = r3;
            }
            #pragma unroll
            for (int mt = 0; mt < 4; mt++)
                #pragma unroll
                for (int nt = 0; nt < 8; nt++)
                    mma16816(acc[mt][nt], af[mt], bf[nt]);
        }
    }

    const int g = lane >> 2, t = lane & 3;
    #pragma unroll
    for (int mt = 0; mt < 4; mt++) {
        #pragma unroll
        for (int nt = 0; nt < 8; nt++) {
            const int col = colBase + wn * 64 + nt * 8 + t * 2;
            const float b0 = bias[col], b1 = bias[col + 1];
            const int row0 = rowBase + wm * 64 + mt * 16 + g;
            float v0 = acc[mt][nt][0] + b0, v1 = acc[mt][nt][1] + b1;
            float v2 = acc[mt][nt][2] + b0, v3 = acc[mt][nt][3] + b1;
            if (F16OUT) {
                *(uint32_t*)(Cf + (size_t)row0 * N + col)       = packhf(v0, v1);
                *(uint32_t*)(Cf + (size_t)(row0 + 8) * N + col) = packhf(v2, v3);
            } else {
                *(float2*)&C[(size_t)row0 * N + col]       = make_float2(v0, v1);
                *(float2*)&C[(size_t)(row0 + 8) * N + col] = make_float2(v2, v3);
            }
        }
    }
}

// ================= tensor-core causal flash attention (fp16, swizzled) =================
// R13 per-tile arithmetic, but TWO 64-key tiles processed per wait+sync on a
// 4-slot buffer ring (nk is always even). Halves barrier/wait overhead and lets
// tile-B's front overlap tile-A's draining PV MMAs.
#define TILEB 8192                    // 64 rows x 128B (SW128)
#define BUFB  (2*TILEB)               // K, V = 16384 B
#define QOFF  (4u*BUFB)               // Q region after 4 ring slots
#define ATT_SMEM (4*BUFB + 16384)     // 81920 B
#define ESC 0.18033688f               // 0.125 * log2(e)

__global__ __launch_bounds__(128, 2)
void attn_mma(const __half* __restrict__ qkv, __half* __restrict__ yf)
{
    extern __shared__ __align__(16) char sm[];
    const uint32_t smBase = smem_u32(sm);

    const int tid  = threadIdx.x;
    const int lane = tid & 31;
    const int wm   = tid >> 5;          // 0..3, rows wm*32..wm*32+31
    const int bh = blockIdx.y;
    const int b  = bh / Hn;
    const int h  = bh % Hn;
    const int q0 = (gridDim.x - 1 - blockIdx.x) * 128;   // big tiles first

    const int mat = lane >> 3, r8 = lane & 7;
    const int g = lane >> 2, t = lane & 3;
    const uint32_t pat = (uint32_t)r8 << 4;

    const int nk = q0 / 64 + 2;     // always even
    const int np = nk >> 1;         // pairs

    // ---- stage Q into Q region (1024 chunks / 128 threads) ----
    #pragma unroll
    for (int i = 0; i < 8; i++) {
        const int idx = tid + i * 128;
        const int r   = idx >> 3;
        const int c8  = idx & 7;
        const uint32_t dst = smBase + QOFF
                           + (uint32_t)(r * 128 + ((c8 * 16) ^ ((r & 7) << 4)));
        const __half* src = qkv + (size_t)(b * Tseq + q0 + r) * C3 + h * HD + c8 * 8;
        CP_ASYNC16(dst, src);
    }
    CP_COMMIT();

    uint32_t kRow[4], kcol[4], qcol[4], vcol[4];
    #pragma unroll
    for (int nt2 = 0; nt2 < 4; nt2++) {
        kRow[nt2] = (uint32_t)(nt2 * 16 + (mat >> 1) * 8 + r8) * 128;
        vcol[nt2] = (uint32_t)(nt2 * 32 + (mat >> 1) * 16) ^ pat;
    }
    #pragma unroll
    for (int ks = 0; ks < 4; ks++) {
        kcol[ks] = (uint32_t)(ks * 32 + (mat & 1) * 16) ^ pat;
        qcol[ks] = (uint32_t)(ks * 32 + (mat >> 1) * 16) ^ pat;
    }
    const uint32_t vRow = (uint32_t)((mat & 1) * 8 + r8) * 128;

    // fill pair j: tiles 2j and 2j+1 (2048 chunks / 128 threads), one commit
    auto fill_pair = [&](int j) {
        #pragma unroll
        for (int i = 0; i < 16; i++) {
            const int idx  = tid + i * 128;
            const int half = idx >> 10;          // 0 -> tile 2j, 1 -> tile 2j+1
            const int rem  = idx & 1023;
            const int tile = rem >> 9;           // 0 K, 1 V
            const int r    = (rem >> 3) & 63;
            const int c8   = rem & 7;
            const int tt   = 2 * j + half;
            const uint32_t dst = smBase + (uint32_t)(tt & 3) * BUFB + (uint32_t)tile * TILEB
                               + (uint32_t)(r * 128 + ((c8 * 16) ^ ((r & 7) << 4)));
            const __half* src = qkv + (size_t)(b * Tseq + tt * 64 + r) * C3 + h * HD + c8 * 8
                              + (tile ? 2 * Cdim : Cdim);
            CP_ASYNC16(dst, src);
        }
        CP_COMMIT();
    };

    fill_pair(0);

    CP_WAIT(1);          // Q group complete (pair0 may be pending)
    __syncthreads();

    uint32_t qf[2][4][4];
    #pragma unroll
    for (int mt = 0; mt < 2; mt++) {
        const uint32_t qRow = (uint32_t)(wm * 32 + mt * 16 + (mat & 1) * 8 + r8) * 128;
        #pragma unroll
        for (int ks = 0; ks < 4; ks++)
            ldsm_x4(qf[mt][ks][0], qf[mt][ks][1], qf[mt][ks][2], qf[mt][ks][3],
                    smBase + QOFF + qRow + qcol[ks]);
    }

    float O[2][8][4];
    #pragma unroll
    for (int mt = 0; mt < 2; mt++)
        #pragma unroll
        for (int nt = 0; nt < 8; nt++)
            #pragma unroll
            for (int q = 0; q < 4; q++) O[mt][nt][q] = 0.f;
    float mm[2][2], ll[2][2];
    #pragma unroll
    for (int mt = 0; mt < 2; mt++) { mm[mt][0] = mm[mt][1] = -1e30f; ll[mt][0] = ll[mt][1] = 0.f; }

    const uint32_t onesb[2] = {0x3C003C00u, 0x3C003C00u};   // fp16 1.0 x4

    // per-tile processing (R13 arithmetic, unchanged)
    auto process_tile = [&](int tt) {
        const int k0 = tt * 64;
        const uint32_t bufO = smBase + (uint32_t)(tt & 3) * BUFB;

        float S[2][8][4];
        #pragma unroll
        for (int mt = 0; mt < 2; mt++)
            #pragma unroll
            for (int nt = 0; nt < 8; nt++)
                #pragma unroll
                for (int q = 0; q < 4; q++) S[mt][nt][q] = 0.f;

        #pragma unroll
        for (int ks = 0; ks < 4; ks++) {
            uint32_t kf[8][2];
            #pragma unroll
            for (int nt2 = 0; nt2 < 4; nt2++) {
                uint32_t r0, r1, r2, r3;
                ldsm_x4(r0, r1, r2, r3, bufO + kRow[nt2] + kcol[ks]);
                kf[nt2*2][0] = r0; kf[nt2*2][1] = r1;
                kf[nt2*2+1][0] = r2; kf[nt2*2+1][1] = r3;
            }
            #pragma unroll
            for (int mt = 0; mt < 2; mt++)
                #pragma unroll
                for (int nt = 0; nt < 8; nt++)
                    mma16816(S[mt][nt], qf[mt][ks], kf[nt]);
        }

        if (k0 + 63 > q0 + wm * 32) {
            #pragma unroll
            for (int mt = 0; mt < 2; mt++) {
                const int rg0 = q0 + wm * 32 + mt * 16 + g;
                const int rg1 = rg0 + 8;
                #pragma unroll
                for (int nt = 0; nt < 8; nt++) {
                    const int c = k0 + nt * 8 + t * 2;
                    if (c     > rg0) S[mt][nt][0] = -1e30f;
                    if (c + 1 > rg0) S[mt][nt][1] = -1e30f;
                    if (c     > rg1) S[mt][nt][2] = -1e30f;
                    if (c + 1 > rg1) S[mt][nt][3] = -1e30f;
                }
            }
        }

        uint32_t pf[2][4][4];
        #pragma unroll
        for (int mt = 0; mt < 2; mt++) {
            float mx0 = -1e30f, mx1 = -1e30f;
            #pragma unroll
            for (int nt = 0; nt < 8; nt++) {
                mx0 = fmaxf(mx0, fmaxf(S[mt][nt][0], S[mt][nt][1]));
                mx1 = fmaxf(mx1, fmaxf(S[mt][nt][2], S[mt][nt][3]));
            }
            mx0 = fmaxf(mx0, __shfl_xor_sync(0xffffffffu, mx0, 1));
            mx0 = fmaxf(mx0, __shfl_xor_sync(0xffffffffu, mx0, 2));
            mx1 = fmaxf(mx1, __shfl_xor_sync(0xffffffffu, mx1, 1));
            mx1 = fmaxf(mx1, __shfl_xor_sync(0xffffffffu, mx1, 2));

            const float mn0 = fmaxf(mm[mt][0], mx0);
            const float mn1 = fmaxf(mm[mt][1], mx1);
            const float cr0 = exp2f((mm[mt][0] - mn0) * ESC);
            const float cr1 = exp2f((mm[mt][1] - mn1) * ESC);
            mm[mt][0] = mn0; mm[mt][1] = mn1;
            #pragma unroll
            for (int nt = 0; nt < 8; nt++) {
                O[mt][nt][0] *= cr0; O[mt][nt][1] *= cr0;
                O[mt][nt][2] *= cr1; O[mt][nt][3] *= cr1;
            }

            const float nE0 = mn0 * ESC, nE1 = mn1 * ESC;
            #pragma unroll
            for (int kk = 0; kk < 4; kk++) {
                pf[mt][kk][0] = ex2_f16x2(packhf(fmaf(S[mt][2*kk][0],   ESC, -nE0), fmaf(S[mt][2*kk][1],   ESC, -nE0)));
                pf[mt][kk][1] = ex2_f16x2(packhf(fmaf(S[mt][2*kk][2],   ESC, -nE1), fmaf(S[mt][2*kk][3],   ESC, -nE1)));
                pf[mt][kk][2] = ex2_f16x2(packhf(fmaf(S[mt][2*kk+1][0], ESC, -nE0), fmaf(S[mt][2*kk+1][1], ESC, -nE0)));
                pf[mt][kk][3] = ex2_f16x2(packhf(fmaf(S[mt][2*kk+1][2], ESC, -nE1), fmaf(S[mt][2*kk+1][3], ESC, -nE1)));
            }

            float lac[4] = {0.f, 0.f, 0.f, 0.f};
            #pragma unroll
            for (int kk = 0; kk < 4; kk++) mma16816(lac, pf[mt][kk], onesb);
            ll[mt][0] = ll[mt][0] * cr0 + lac[0];
            ll[mt][1] = ll[mt][1] * cr1 + lac[2];
        }

        #pragma unroll
        for (int kk = 0; kk < 4; kk++) {
            uint32_t vf[8][2];
            #pragma unroll
            for (int nd2 = 0; nd2 < 4; nd2++) {
                uint32_t r0, r1, r2, r3;
                ldsm_x4_t(r0, r1, r2, r3, bufO + TILEB + vRow + kk * 2048 + vcol[nd2]);
                vf[nd2*2][0] = r0; vf[nd2*2][1] = r1;
                vf[nd2*2+1][0] = r2; vf[nd2*2+1][1] = r3;
            }
            #pragma unroll
            for (int mt = 0; mt < 2; mt++)
                #pragma unroll
                for (int nd = 0; nd < 8; nd++)
                    mma16816(O[mt][nd], pf[mt][kk], vf[nd]);
        }
    };

    for (int j = 0; j < np; ++j) {
        CP_WAIT(0);                      // pair j complete
        __syncthreads();                 // visible to all; pair j-1 fully consumed
        if (j + 1 < np) fill_pair(j + 1);   // lands in pair j-1's slots

        process_tile(2 * j);
        process_tile(2 * j + 1);
    }

    // ---- epilogue: normalize, round to fp16, store ----
    #pragma unroll
    for (int mt = 0; mt < 2; mt++) {
        const float i0 = 1.f / ll[mt][0], i1 = 1.f / ll[mt][1];
        const int rg0 = q0 + wm * 32 + mt * 16 + g;
        const size_t base0 = (size_t)(b * Tseq + rg0) * Cdim + h * HD;
        const size_t base1 = (size_t)(b * Tseq + rg0 + 8) * Cdim + h * HD;
        #pragma unroll
        for (int nt = 0; nt < 8; nt++) {
            const int col = nt * 8 + t * 2;
            *(uint32_t*)(yf + base0 + col) = packhf(O[mt][nt][0] * i0, O[mt][nt][1] * i0);
            *(uint32_t*)(yf + base1 + col) = packhf(O[mt][nt][2] * i1, O[mt][nt][3] * i1);
        }
    }
}

// ---------------- launch ----------------
extern "C" void kernel_launch(void* const* d_in, const int* in_sizes, int n_in,
                              void* d_out, int out_size)
{
    const float* x     = (const float*)d_in[0];
    const float* qkv_w = (const float*)d_in[1];
    const float* qkv_b = (const float*)d_in[2];
    const float* out_w = (const float*)d_in[3];
    const float* out_b = (const float*)d_in[4];
    float* out = (float*)d_out;

    __half *xf, *qkvf, *yf, *wqf, *wof;
    cudaGetSymbolAddress((void**)&xf,   g_xf);
    cudaGetSymbolAddress((void**)&qkvf, g_qkvf);
    cudaGetSymbolAddress((void**)&yf,   g_yf);
    cudaGetSymbolAddress((void**)&wqf,  g_wqf);
    cudaGetSymbolAddress((void**)&wof,  g_wof);

    cudaFuncSetAttribute(gemm_mma<true>,  cudaFuncAttributeMaxDynamicSharedMemorySize, GEMM_SMEM);
    cudaFuncSetAttribute(gemm_mma<false>, cudaFuncAttributeMaxDynamicSharedMemorySize, GEMM_SMEM);
    cudaFuncSetAttribute(attn_mma, cudaFuncAttributeMaxDynamicSharedMemorySize, ATT_SMEM);

    const int M = Mrows;   // 8192

    // 0) fused prep
    prep_kernel<<<XB + WQB + WOB, 256>>>(x, xf, qkv_w, wqf, out_w, wof);

    // 1) QKV projection -> fp16 qkv
    gemm_mma<true><<<dim3(C3 / GBN, M / GBM), 128, GEMM_SMEM>>>(
        xf, wqf, qkv_b, nullptr, qkvf, M, C3, Cdim);

    // 2) causal attention -> fp16 y (paired-tile processing)
    attn_mma<<<dim3(Tseq / 128, Bsz * Hn), 128, ATT_SMEM>>>(qkvf, yf);

    // 3) output projection -> fp32 out
    gemm_mma<false><<<dim3(Cdim / GBN, M / GBM), 128, GEMM_SMEM>>>(
        yf, wof, out_b, out, nullptr, M, Cdim, Cdim);
}